// round 8
// baseline (speedup 1.0000x reference)
#include <cuda_runtime.h>

static constexpr int NPIX   = 256 * 256;   // pixels per batch
static constexpr int NBATCH = 16;
static constexpr int NBINS  = 64;
static constexpr int BPB    = 9;           // blocks per batch (9*16=144 ~ one wave)
static constexpr int TPB    = 256;

// encoded global min/max: [ref_min, ref_max, tar_min, tar_max]
__device__ unsigned g_mm[4];

// Monotone float->uint encoding (works for negatives too)
__device__ __forceinline__ unsigned fenc(float f) {
    unsigned b = __float_as_uint(f);
    return (b & 0x80000000u) ? ~b : (b | 0x80000000u);
}
__device__ __forceinline__ float fdec(unsigned e) {
    unsigned b = (e & 0x80000000u) ? (e & 0x7fffffffu) : ~e;
    return __uint_as_float(b);
}

__global__ void k_init(float* __restrict__ out, int n) {
    int i = blockIdx.x * blockDim.x + threadIdx.x;
    if (i < n) out[i] = 0.0f;
    if (i == 0) {
        g_mm[0] = 0xFFFFFFFFu; g_mm[1] = 0u;   // ref min/max
        g_mm[2] = 0xFFFFFFFFu; g_mm[3] = 0u;   // tar min/max
    }
}

__global__ void k_minmax(const float4* __restrict__ ref,
                         const float4* __restrict__ tar, int n4) {
    unsigned rmin = 0xFFFFFFFFu, rmax = 0u, tmin = 0xFFFFFFFFu, tmax = 0u;
    for (int i = blockIdx.x * blockDim.x + threadIdx.x; i < n4;
         i += gridDim.x * blockDim.x) {
        float4 a = ref[i];
        unsigned e;
        e = fenc(a.x); rmin = min(rmin, e); rmax = max(rmax, e);
        e = fenc(a.y); rmin = min(rmin, e); rmax = max(rmax, e);
        e = fenc(a.z); rmin = min(rmin, e); rmax = max(rmax, e);
        e = fenc(a.w); rmin = min(rmin, e); rmax = max(rmax, e);
        float4 b = tar[i];
        e = fenc(b.x); tmin = min(tmin, e); tmax = max(tmax, e);
        e = fenc(b.y); tmin = min(tmin, e); tmax = max(tmax, e);
        e = fenc(b.z); tmin = min(tmin, e); tmax = max(tmax, e);
        e = fenc(b.w); tmin = min(tmin, e); tmax = max(tmax, e);
    }
    #pragma unroll
    for (int o = 16; o > 0; o >>= 1) {
        rmin = min(rmin, __shfl_xor_sync(0xFFFFFFFFu, rmin, o));
        rmax = max(rmax, __shfl_xor_sync(0xFFFFFFFFu, rmax, o));
        tmin = min(tmin, __shfl_xor_sync(0xFFFFFFFFu, tmin, o));
        tmax = max(tmax, __shfl_xor_sync(0xFFFFFFFFu, tmax, o));
    }
    if ((threadIdx.x & 31) == 0) {
        atomicMin(&g_mm[0], rmin);
        atomicMax(&g_mm[1], rmax);
        atomicMin(&g_mm[2], tmin);
        atomicMax(&g_mm[3], tmax);
    }
}

// Closed-form cubic B-spline weights at offsets {-1-u, -u, 1-u, 2-u}
__device__ __forceinline__ void bsw(float u, float w[4]) {
    float v = 1.0f - u;
    w[0] = v * v * v * (1.0f / 6.0f);                 // bin f-1
    w[1] = 2.0f / 3.0f - u * u * (1.0f - 0.5f * u);   // bin f
    w[2] = 2.0f / 3.0f - v * v * (1.0f - 0.5f * v);   // bin f+1
    w[3] = u * u * u * (1.0f / 6.0f);                 // bin f+2
}

__device__ __forceinline__ void accum(float r, float t,
                                      float rmin, float rs,
                                      float tmin, float ts,
                                      float* __restrict__ sh) {
    float fr = (r - rmin) * rs;          // in [0, 64]
    float ft = (t - tmin) * ts;
    float fir = floorf(fr), fit = floorf(ft);
    float ur = fr - fir,   ut = ft - fit;
    int br = (int)fir - 1, bt = (int)fit - 1;
    float wr[4], wt[4];
    bsw(ur, wr);
    bsw(ut, wt);
    #pragma unroll
    for (int i = 0; i < 4; i++) {
        int bi = br + i;
        if ((unsigned)bi >= (unsigned)NBINS) continue;
        float wrv = wr[i];
        #pragma unroll
        for (int j = 0; j < 4; j++) {
            int bj = bt + j;
            if ((unsigned)bj >= (unsigned)NBINS) continue;
            atomicAdd(&sh[bi * NBINS + bj], wrv * wt[j]);
        }
    }
}

__global__ __launch_bounds__(TPB)
void k_hist(const float4* __restrict__ ref,
            const float4* __restrict__ tar,
            float* __restrict__ out) {
    __shared__ float sh[NBINS * NBINS];
    const int batch = blockIdx.y;

    for (int i = threadIdx.x; i < NBINS * NBINS; i += TPB) sh[i] = 0.0f;
    __syncthreads();

    const float rmin = fdec(g_mm[0]);
    const float rmax = fdec(g_mm[1]);
    const float tmin = fdec(g_mm[2]);
    const float tmax = fdec(g_mm[3]);
    const float rs = 64.0f / (rmax - rmin);
    const float ts = 64.0f / (tmax - tmin);

    const float4* rp = ref + (size_t)batch * (NPIX / 4);
    const float4* tp = tar + (size_t)batch * (NPIX / 4);

    for (int i = blockIdx.x * TPB + threadIdx.x; i < NPIX / 4; i += BPB * TPB) {
        float4 r4 = rp[i];
        float4 t4 = tp[i];
        accum(r4.x, t4.x, rmin, rs, tmin, ts, sh);
        accum(r4.y, t4.y, rmin, rs, tmin, ts, sh);
        accum(r4.z, t4.z, rmin, rs, tmin, ts, sh);
        accum(r4.w, t4.w, rmin, rs, tmin, ts, sh);
    }
    __syncthreads();

    float* o = out + (size_t)batch * NBINS * NBINS;
    for (int i = threadIdx.x; i < NBINS * NBINS; i += TPB) {
        // / (EPS*EPS) = * 4096
        atomicAdd(&o[i], sh[i] * 4096.0f);
    }
}

extern "C" void kernel_launch(void* const* d_in, const int* in_sizes, int n_in,
                              void* d_out, int out_size) {
    const float* img_ref = (const float*)d_in[0];
    const float* img_tar = (const float*)d_in[1];
    float* out = (float*)d_out;

    // 1) zero output + reset min/max cells
    k_init<<<(out_size + 255) / 256, 256>>>(out, out_size);

    // 2) global min/max over each full image (NBATCH*NPIX elements each)
    const int n4 = NBATCH * NPIX / 4;
    k_minmax<<<296, 256>>>((const float4*)img_ref, (const float4*)img_tar, n4);

    // 3) joint histogram
    dim3 grid(BPB, NBATCH);
    k_hist<<<grid, TPB>>>((const float4*)img_ref, (const float4*)img_tar, out);
}

// round 9
// speedup vs baseline: 1.0869x; 1.0869x over previous
#include <cuda_runtime.h>

static constexpr int NPIX   = 256 * 256;     // pixels per batch
static constexpr int NBATCH = 16;
static constexpr int NBINS  = 64;
static constexpr int QUADS  = NBINS / 4;     // 16 u64 words per ref-row
static constexpr int BPB    = 9;             // blocks per batch
static constexpr int NBLK   = BPB * NBATCH;  // 144 blocks <= 148 SMs (co-resident)
static constexpr int TPB    = 256;
static constexpr int OUT_N  = NBATCH * NBINS * NBINS;

// Per-block min/max slots (plain overwrite each call -> no reset needed)
__device__ unsigned g_slot[NBLK][4];
// Monotone arrival counter (never reset; round target derived from own ticket)
__device__ unsigned g_cnt;

// Monotone float->uint encoding
__device__ __forceinline__ unsigned fenc(float f) {
    unsigned b = __float_as_uint(f);
    return (b & 0x80000000u) ? ~b : (b | 0x80000000u);
}
__device__ __forceinline__ float fdec(unsigned e) {
    unsigned b = (e & 0x80000000u) ? (e & 0x7fffffffu) : ~e;
    return __uint_as_float(b);
}

// One pixel: 4x4 B-spline outer product -> packed 16-bit fixed-point (scale 4096)
// into u64 quad-words of the shared histogram. ~7 shared atomics per pixel.
__device__ __forceinline__ void accum(float r, float t,
                                      float rmin, float rs,
                                      float tmin, float ts,
                                      unsigned long long* __restrict__ sh)
{
    float fr = (r - rmin) * rs;              // in [0, 64]
    float ft = (t - tmin) * ts;
    float fir = floorf(fr), fit = floorf(ft);
    float ur = fr - fir,   ut = ft - fit;
    int br = (int)fir - 1, bt = (int)fit - 1;

    float vr = 1.0f - ur, vt = 1.0f - ut;
    float urr = ur * ur, vrr = vr * vr, utt = ut * ut, vtt = vt * vt;

    float wr[4];
    wr[0] = vrr * vr * (1.0f / 6.0f);
    wr[1] = fmaf(-urr, fmaf(-0.5f, ur, 1.0f), 2.0f / 3.0f);
    wr[2] = fmaf(-vrr, fmaf(-0.5f, vr, 1.0f), 2.0f / 3.0f);
    wr[3] = urr * ur * (1.0f / 6.0f);

    // tar weights pre-scaled by 4096 (= 1/EPS^2 folded into the fixed point)
    float wt0 = vtt * vt * (4096.0f / 6.0f);
    float wt1 = fmaf(-utt, fmaf(-0.5f, ut, 1.0f), 2.0f / 3.0f) * 4096.0f;
    float wt2 = fmaf(-vtt, fmaf(-0.5f, vt, 1.0f), 2.0f / 3.0f) * 4096.0f;
    float wt3 = utt * ut * (4096.0f / 6.0f);

    const float MAGIC = 12582912.0f;         // 1.5 * 2^23: round-to-nearest int in mantissa
    int q0 = bt >> 2;                        // arithmetic shift: floor div (bt may be -2..-1)
    int s  = (bt & 3) << 4;                  // bit shift within 128-bit window

    #pragma unroll
    for (int i = 0; i < 4; i++) {
        int bi = br + i;
        if ((unsigned)bi >= (unsigned)NBINS) continue;
        float w = wr[i];
        unsigned m0 = __float_as_uint(fmaf(w, wt0, MAGIC));
        unsigned m1 = __float_as_uint(fmaf(w, wt1, MAGIC));
        unsigned m2 = __float_as_uint(fmaf(w, wt2, MAGIC));
        unsigned m3 = __float_as_uint(fmaf(w, wt3, MAGIC));
        unsigned lo = __byte_perm(m0, m1, 0x5410);   // m0[15:0] | m1[15:0]<<16
        unsigned hi = __byte_perm(m2, m3, 0x5410);
        unsigned long long P = ((unsigned long long)hi << 32) | lo;
        unsigned long long* row = sh + bi * QUADS;
        if (s == 0) {
            atomicAdd(&row[q0], P);
        } else {
            if (q0 >= 0)        atomicAdd(&row[q0],     P << s);
            if (q0 < QUADS - 1) atomicAdd(&row[q0 + 1], P >> (64 - s));
        }
    }
}

__global__ __launch_bounds__(TPB)
void k_fused(const float4* __restrict__ ref,
             const float4* __restrict__ tar,
             float* __restrict__ out)
{
    __shared__ unsigned long long sh[NBINS * QUADS];   // 8 KB packed histogram
    __shared__ unsigned s_mm[4];
    const int tid = threadIdx.x;
    const int bid = blockIdx.x;
    const int lane = tid & 31;

    // ---- phase 0: zero output slice + shared hist + smem minmax cells ----
    for (int i = bid * TPB + tid; i < OUT_N; i += NBLK * TPB) out[i] = 0.0f;
    for (int i = tid; i < NBINS * QUADS; i += TPB) sh[i] = 0ull;
    if (tid < 4) s_mm[tid] = (tid & 1) ? 0u : 0xFFFFFFFFu;

    // ---- phase 1: global min/max over both full images ----
    unsigned rmn = 0xFFFFFFFFu, rmx = 0u, tmn = 0xFFFFFFFFu, tmx = 0u;
    const int n4 = NBATCH * NPIX / 4;
    for (int i = bid * TPB + tid; i < n4; i += NBLK * TPB) {
        float4 a = ref[i];
        unsigned e;
        e = fenc(a.x); rmn = min(rmn, e); rmx = max(rmx, e);
        e = fenc(a.y); rmn = min(rmn, e); rmx = max(rmx, e);
        e = fenc(a.z); rmn = min(rmn, e); rmx = max(rmx, e);
        e = fenc(a.w); rmn = min(rmn, e); rmx = max(rmx, e);
        float4 b = tar[i];
        e = fenc(b.x); tmn = min(tmn, e); tmx = max(tmx, e);
        e = fenc(b.y); tmn = min(tmn, e); tmx = max(tmx, e);
        e = fenc(b.z); tmn = min(tmn, e); tmx = max(tmx, e);
        e = fenc(b.w); tmn = min(tmn, e); tmx = max(tmx, e);
    }
    #pragma unroll
    for (int o = 16; o > 0; o >>= 1) {
        rmn = min(rmn, __shfl_xor_sync(0xFFFFFFFFu, rmn, o));
        rmx = max(rmx, __shfl_xor_sync(0xFFFFFFFFu, rmx, o));
        tmn = min(tmn, __shfl_xor_sync(0xFFFFFFFFu, tmn, o));
        tmx = max(tmx, __shfl_xor_sync(0xFFFFFFFFu, tmx, o));
    }
    __syncthreads();                       // s_mm initialized, zero-stores issued
    if (lane == 0) {
        atomicMin(&s_mm[0], rmn); atomicMax(&s_mm[1], rmx);
        atomicMin(&s_mm[2], tmn); atomicMax(&s_mm[3], tmx);
    }
    __threadfence();                       // release: out-zero stores globally visible
    __syncthreads();

    // ---- grid sync (all 144 CTAs co-resident -> spin is safe) ----
    if (tid == 0) {
        volatile unsigned* sl = g_slot[bid];
        sl[0] = s_mm[0]; sl[1] = s_mm[1]; sl[2] = s_mm[2]; sl[3] = s_mm[3];
        __threadfence();
        unsigned prev = atomicAdd(&g_cnt, 1);
        unsigned target = prev - (prev % NBLK) + NBLK;   // end of this round
        while (*(volatile unsigned*)&g_cnt < target) { }
        __threadfence();                   // acquire
    }
    __syncthreads();

    // ---- reduce all block slots -> global min/max ----
    if (tid < 4) s_mm[tid] = (tid & 1) ? 0u : 0xFFFFFFFFu;
    __syncthreads();
    if (tid < NBLK) {
        volatile unsigned* sl = g_slot[tid];
        unsigned a0 = sl[0], a1 = sl[1], a2 = sl[2], a3 = sl[3];
        atomicMin(&s_mm[0], a0); atomicMax(&s_mm[1], a1);
        atomicMin(&s_mm[2], a2); atomicMax(&s_mm[3], a3);
    }
    __syncthreads();

    const float rmin = fdec(s_mm[0]), rmax = fdec(s_mm[1]);
    const float tmin = fdec(s_mm[2]), tmax = fdec(s_mm[3]);
    const float rs = 64.0f / (rmax - rmin);
    const float ts = 64.0f / (tmax - tmin);

    // ---- phase 2: per-batch joint histogram (images now L2-resident) ----
    const int batch = bid / BPB, sub = bid % BPB;
    const float4* rp = ref + (size_t)batch * (NPIX / 4);
    const float4* tp = tar + (size_t)batch * (NPIX / 4);
    for (int i = sub * TPB + tid; i < NPIX / 4; i += BPB * TPB) {
        float4 r4 = rp[i];
        float4 t4 = tp[i];
        accum(r4.x, t4.x, rmin, rs, tmin, ts, sh);
        accum(r4.y, t4.y, rmin, rs, tmin, ts, sh);
        accum(r4.z, t4.z, rmin, rs, tmin, ts, sh);
        accum(r4.w, t4.w, rmin, rs, tmin, ts, sh);
    }
    __syncthreads();

    // ---- phase 3: unpack fields (scale 4096 == 1/EPS^2) and flush to out ----
    float* o = out + (size_t)batch * NBINS * NBINS;
    for (int q = tid; q < NBINS * QUADS; q += TPB) {
        unsigned long long h = sh[q];
        if (h) {
            float* c = o + q * 4;
            atomicAdd(c + 0, (float)(unsigned)( h        & 0xFFFFu));
            atomicAdd(c + 1, (float)(unsigned)((h >> 16) & 0xFFFFu));
            atomicAdd(c + 2, (float)(unsigned)((h >> 32) & 0xFFFFu));
            atomicAdd(c + 3, (float)(unsigned)( h >> 48));
        }
    }
}

extern "C" void kernel_launch(void* const* d_in, const int* in_sizes, int n_in,
                              void* d_out, int out_size) {
    const float4* img_ref = (const float4*)d_in[0];
    const float4* img_tar = (const float4*)d_in[1];
    float* out = (float*)d_out;
    k_fused<<<NBLK, TPB>>>(img_ref, img_tar, out);
}

// round 10
// speedup vs baseline: 1.7165x; 1.5792x over previous
#include <cuda_runtime.h>

static constexpr int NPIX   = 256 * 256;     // pixels per batch
static constexpr int NBATCH = 16;
static constexpr int NBINS  = 64;
static constexpr int QUADS  = NBINS / 4;     // 16 u64 words per ref-row
static constexpr int BPB    = 9;             // blocks per batch
static constexpr int NBLK   = BPB * NBATCH;  // 144 blocks <= 148 SMs (co-resident)
static constexpr int TPB    = 1024;          // 32 warps/SM -> hide ALU/ATOMS latency
static constexpr int OUT_N  = NBATCH * NBINS * NBINS;

// Per-block min/max slots (plain overwrite each call -> no reset needed)
__device__ unsigned g_slot[NBLK][4];
// Monotone arrival counter (never reset; round target derived from own ticket)
__device__ unsigned g_cnt;

// Monotone float->uint encoding
__device__ __forceinline__ unsigned fenc(float f) {
    unsigned b = __float_as_uint(f);
    return (b & 0x80000000u) ? ~b : (b | 0x80000000u);
}
__device__ __forceinline__ float fdec(unsigned e) {
    unsigned b = (e & 0x80000000u) ? (e & 0x7fffffffu) : ~e;
    return __uint_as_float(b);
}

// One pixel: 4x4 B-spline outer product -> packed 16-bit fixed-point (scale 4096)
// into u64 quad-words of the shared histogram. ~7 shared atomics per pixel.
__device__ __forceinline__ void accum(float r, float t,
                                      float rmin, float rs,
                                      float tmin, float ts,
                                      unsigned long long* __restrict__ sh)
{
    float fr = (r - rmin) * rs;              // in [0, 64]
    float ft = (t - tmin) * ts;
    float fir = floorf(fr), fit = floorf(ft);
    float ur = fr - fir,   ut = ft - fit;
    int br = (int)fir - 1, bt = (int)fit - 1;

    float vr = 1.0f - ur, vt = 1.0f - ut;
    float urr = ur * ur, vrr = vr * vr, utt = ut * ut, vtt = vt * vt;

    float wr[4];
    wr[0] = vrr * vr * (1.0f / 6.0f);
    wr[1] = fmaf(-urr, fmaf(-0.5f, ur, 1.0f), 2.0f / 3.0f);
    wr[2] = fmaf(-vrr, fmaf(-0.5f, vr, 1.0f), 2.0f / 3.0f);
    wr[3] = urr * ur * (1.0f / 6.0f);

    // tar weights pre-scaled by 4096 (= 1/EPS^2 folded into the fixed point)
    float wt0 = vtt * vt * (4096.0f / 6.0f);
    float wt1 = fmaf(-utt, fmaf(-0.5f, ut, 1.0f), 2.0f / 3.0f) * 4096.0f;
    float wt2 = fmaf(-vtt, fmaf(-0.5f, vt, 1.0f), 2.0f / 3.0f) * 4096.0f;
    float wt3 = utt * ut * (4096.0f / 6.0f);

    const float MAGIC = 12582912.0f;         // 1.5 * 2^23: round-to-nearest in mantissa
    int q0 = bt >> 2;                        // arithmetic shift: floor div (bt may be -2..-1)
    int s  = (bt & 3) << 4;                  // bit shift within 128-bit window

    #pragma unroll
    for (int i = 0; i < 4; i++) {
        int bi = br + i;
        if ((unsigned)bi >= (unsigned)NBINS) continue;
        float w = wr[i];
        unsigned m0 = __float_as_uint(fmaf(w, wt0, MAGIC));
        unsigned m1 = __float_as_uint(fmaf(w, wt1, MAGIC));
        unsigned m2 = __float_as_uint(fmaf(w, wt2, MAGIC));
        unsigned m3 = __float_as_uint(fmaf(w, wt3, MAGIC));
        unsigned lo = __byte_perm(m0, m1, 0x5410);   // m0[15:0] | m1[15:0]<<16
        unsigned hi = __byte_perm(m2, m3, 0x5410);
        unsigned long long P = ((unsigned long long)hi << 32) | lo;
        unsigned long long* row = sh + bi * QUADS;
        if (s == 0) {
            atomicAdd(&row[q0], P);
        } else {
            if (q0 >= 0)        atomicAdd(&row[q0],     P << s);
            if (q0 < QUADS - 1) atomicAdd(&row[q0 + 1], P >> (64 - s));
        }
    }
}

__global__ __launch_bounds__(TPB)
void k_fused(const float4* __restrict__ ref,
             const float4* __restrict__ tar,
             float* __restrict__ out)
{
    __shared__ unsigned long long sh[NBINS * QUADS];   // 8 KB packed histogram
    __shared__ unsigned s_mm[4];
    const int tid = threadIdx.x;
    const int bid = blockIdx.x;
    const int lane = tid & 31;

    // ---- phase 0: zero output slice + shared hist + smem minmax cells ----
    for (int i = bid * TPB + tid; i < OUT_N; i += NBLK * TPB) out[i] = 0.0f;
    for (int i = tid; i < NBINS * QUADS; i += TPB) sh[i] = 0ull;
    if (tid < 4) s_mm[tid] = (tid & 1) ? 0u : 0xFFFFFFFFu;

    // ---- phase 1: global min/max over both full images ----
    unsigned rmn = 0xFFFFFFFFu, rmx = 0u, tmn = 0xFFFFFFFFu, tmx = 0u;
    const int n4 = NBATCH * NPIX / 4;
    for (int i = bid * TPB + tid; i < n4; i += NBLK * TPB) {
        float4 a = ref[i];
        unsigned e;
        e = fenc(a.x); rmn = min(rmn, e); rmx = max(rmx, e);
        e = fenc(a.y); rmn = min(rmn, e); rmx = max(rmx, e);
        e = fenc(a.z); rmn = min(rmn, e); rmx = max(rmx, e);
        e = fenc(a.w); rmn = min(rmn, e); rmx = max(rmx, e);
        float4 b = tar[i];
        e = fenc(b.x); tmn = min(tmn, e); tmx = max(tmx, e);
        e = fenc(b.y); tmn = min(tmn, e); tmx = max(tmx, e);
        e = fenc(b.z); tmn = min(tmn, e); tmx = max(tmx, e);
        e = fenc(b.w); tmn = min(tmn, e); tmx = max(tmx, e);
    }
    #pragma unroll
    for (int o = 16; o > 0; o >>= 1) {
        rmn = min(rmn, __shfl_xor_sync(0xFFFFFFFFu, rmn, o));
        rmx = max(rmx, __shfl_xor_sync(0xFFFFFFFFu, rmx, o));
        tmn = min(tmn, __shfl_xor_sync(0xFFFFFFFFu, tmn, o));
        tmx = max(tmx, __shfl_xor_sync(0xFFFFFFFFu, tmx, o));
    }
    __syncthreads();                       // s_mm initialized, zero-stores issued
    if (lane == 0) {
        atomicMin(&s_mm[0], rmn); atomicMax(&s_mm[1], rmx);
        atomicMin(&s_mm[2], tmn); atomicMax(&s_mm[3], tmx);
    }
    __threadfence();                       // release: out-zero stores globally visible
    __syncthreads();

    // ---- grid sync (all 144 CTAs co-resident: 1 CTA/SM) ----
    if (tid == 0) {
        volatile unsigned* sl = g_slot[bid];
        sl[0] = s_mm[0]; sl[1] = s_mm[1]; sl[2] = s_mm[2]; sl[3] = s_mm[3];
        __threadfence();
        unsigned prev = atomicAdd(&g_cnt, 1);
        unsigned target = prev - (prev % NBLK) + NBLK;   // end of this round
        while (*(volatile unsigned*)&g_cnt < target) { }
        __threadfence();                   // acquire
    }
    __syncthreads();

    // ---- reduce all block slots -> global min/max ----
    if (tid < 4) s_mm[tid] = (tid & 1) ? 0u : 0xFFFFFFFFu;
    __syncthreads();
    if (tid < NBLK) {
        volatile unsigned* sl = g_slot[tid];
        unsigned a0 = sl[0], a1 = sl[1], a2 = sl[2], a3 = sl[3];
        atomicMin(&s_mm[0], a0); atomicMax(&s_mm[1], a1);
        atomicMin(&s_mm[2], a2); atomicMax(&s_mm[3], a3);
    }
    __syncthreads();

    const float rmin = fdec(s_mm[0]), rmax = fdec(s_mm[1]);
    const float tmin = fdec(s_mm[2]), tmax = fdec(s_mm[3]);
    const float rs = 64.0f / (rmax - rmin);
    const float ts = 64.0f / (tmax - tmin);

    // ---- phase 2: per-batch joint histogram (images now L2-resident) ----
    const int batch = bid / BPB, sub = bid % BPB;
    const float4* rp = ref + (size_t)batch * (NPIX / 4);
    const float4* tp = tar + (size_t)batch * (NPIX / 4);
    for (int i = sub * TPB + tid; i < NPIX / 4; i += BPB * TPB) {
        float4 r4 = rp[i];
        float4 t4 = tp[i];
        accum(r4.x, t4.x, rmin, rs, tmin, ts, sh);
        accum(r4.y, t4.y, rmin, rs, tmin, ts, sh);
        accum(r4.z, t4.z, rmin, rs, tmin, ts, sh);
        accum(r4.w, t4.w, rmin, rs, tmin, ts, sh);
    }
    __syncthreads();

    // ---- phase 3: unpack fields (scale 4096 == 1/EPS^2) and flush to out ----
    float* o = out + (size_t)batch * NBINS * NBINS;
    for (int q = tid; q < NBINS * QUADS; q += TPB) {
        unsigned long long h = sh[q];
        if (h) {
            float* c = o + q * 4;
            atomicAdd(c + 0, (float)(unsigned)( h        & 0xFFFFu));
            atomicAdd(c + 1, (float)(unsigned)((h >> 16) & 0xFFFFu));
            atomicAdd(c + 2, (float)(unsigned)((h >> 32) & 0xFFFFu));
            atomicAdd(c + 3, (float)(unsigned)( h >> 48));
        }
    }
}

extern "C" void kernel_launch(void* const* d_in, const int* in_sizes, int n_in,
                              void* d_out, int out_size) {
    const float4* img_ref = (const float4*)d_in[0];
    const float4* img_tar = (const float4*)d_in[1];
    float* out = (float*)d_out;
    k_fused<<<NBLK, TPB>>>(img_ref, img_tar, out);
}

// round 11
// speedup vs baseline: 2.9025x; 1.6909x over previous
#include <cuda_runtime.h>

static constexpr int NPIX   = 256 * 256;     // pixels per batch
static constexpr int NBATCH = 16;
static constexpr int NBINS  = 64;
static constexpr int BPB    = 9;             // blocks per batch
static constexpr int NBLK   = BPB * NBATCH;  // 144 blocks <= 148 SMs (co-resident)
static constexpr int TPB    = 1024;
static constexpr int OUT_N  = NBATCH * NBINS * NBINS;

// Shift-replicated packed histogram geometry:
// replica r stores bin b at word (b+r)>>2, 16-bit field (b+r)&3.
// Valid bin range written: -1..66 -> word index 0..16 -> 17 words/row.
static constexpr int ROWW = 17;              // u64 words per ref-row
static constexpr int REPW = NBINS * ROWW;    // words per replica (1088)
static constexpr int HWORDS = 4 * REPW;      // 4352 u64 = 34 KB

// Per-block min/max slots (plain overwrite each call -> no reset needed)
__device__ unsigned g_slot[NBLK][4];
// Monotone arrival counter (never reset; round target derived from own ticket)
__device__ unsigned g_cnt;

__device__ __forceinline__ unsigned fenc(float f) {
    unsigned b = __float_as_uint(f);
    return (b & 0x80000000u) ? ~b : (b | 0x80000000u);
}
__device__ __forceinline__ float fdec(unsigned e) {
    unsigned b = (e & 0x80000000u) ? (e & 0x7fffffffu) : ~e;
    return __uint_as_float(b);
}

// One pixel: 4x4 B-spline outer product. Tar window packed into ONE aligned
// u64 per ref row via the shift-replica trick -> exactly 4 smem atomics.
__device__ __forceinline__ void accum(float r, float t,
                                      float rmin, float rs,
                                      float tmin, float ts,
                                      unsigned long long* __restrict__ sh)
{
    float fr = (r - rmin) * rs;              // in [0, 64]
    float ft = (t - tmin) * ts;
    float fir = floorf(fr), fit = floorf(ft);
    float ur = fr - fir,   ut = ft - fit;
    int br = (int)fir - 1;                   // -1..63
    int bt = (int)fit - 1;                   // -1..63

    float vr = 1.0f - ur, vt = 1.0f - ut;
    float urr = ur * ur, vrr = vr * vr, utt = ut * ut, vtt = vt * vt;

    float wr[4];
    wr[0] = vrr * vr * (1.0f / 6.0f);
    wr[1] = fmaf(-urr, fmaf(-0.5f, ur, 1.0f), 2.0f / 3.0f);
    wr[2] = fmaf(-vrr, fmaf(-0.5f, vr, 1.0f), 2.0f / 3.0f);
    wr[3] = urr * ur * (1.0f / 6.0f);

    // tar weights pre-scaled by 4096 (= 1/EPS^2 folded into the fixed point)
    float wt0 = vtt * vt * (4096.0f / 6.0f);
    float wt1 = fmaf(-utt, fmaf(-0.5f, ut, 1.0f), 2.0f / 3.0f) * 4096.0f;
    float wt2 = fmaf(-vtt, fmaf(-0.5f, vt, 1.0f), 2.0f / 3.0f) * 4096.0f;
    float wt3 = utt * ut * (4096.0f / 6.0f);

    const float MAGIC = 12582912.0f;         // 1.5 * 2^23: round-to-nearest in mantissa
    int rep  = (-bt) & 3;                    // replica in which this window is aligned
    int word = (bt + rep) >> 2;              // 0..16
    unsigned long long* base = sh + rep * REPW + word;

    #pragma unroll
    for (int i = 0; i < 4; i++) {
        int bi = br + i;
        if ((unsigned)bi >= (unsigned)NBINS) continue;
        float w = wr[i];
        unsigned m0 = __float_as_uint(fmaf(w, wt0, MAGIC));
        unsigned m1 = __float_as_uint(fmaf(w, wt1, MAGIC));
        unsigned m2 = __float_as_uint(fmaf(w, wt2, MAGIC));
        unsigned m3 = __float_as_uint(fmaf(w, wt3, MAGIC));
        unsigned lo = __byte_perm(m0, m1, 0x5410);
        unsigned hi = __byte_perm(m2, m3, 0x5410);
        unsigned long long P = ((unsigned long long)hi << 32) | lo;
        atomicAdd(base + bi * ROWW, P);
    }
}

__global__ __launch_bounds__(TPB)
void k_fused(const float4* __restrict__ ref,
             const float4* __restrict__ tar,
             float* __restrict__ out)
{
    __shared__ unsigned long long sh[HWORDS];   // 34 KB: 4 shift-replicas
    __shared__ unsigned s_mm[4];
    const int tid = threadIdx.x;
    const int bid = blockIdx.x;
    const int lane = tid & 31;

    // ---- phase 0: zero output slice + shared hist + smem minmax cells ----
    for (int i = bid * TPB + tid; i < OUT_N; i += NBLK * TPB) out[i] = 0.0f;
    for (int i = tid; i < HWORDS; i += TPB) sh[i] = 0ull;
    if (tid < 4) s_mm[tid] = (tid & 1) ? 0u : 0xFFFFFFFFu;

    // ---- phase 1: global min/max over both full images ----
    unsigned rmn = 0xFFFFFFFFu, rmx = 0u, tmn = 0xFFFFFFFFu, tmx = 0u;
    const int n4 = NBATCH * NPIX / 4;
    for (int i = bid * TPB + tid; i < n4; i += NBLK * TPB) {
        float4 a = ref[i];
        unsigned e;
        e = fenc(a.x); rmn = min(rmn, e); rmx = max(rmx, e);
        e = fenc(a.y); rmn = min(rmn, e); rmx = max(rmx, e);
        e = fenc(a.z); rmn = min(rmn, e); rmx = max(rmx, e);
        e = fenc(a.w); rmn = min(rmn, e); rmx = max(rmx, e);
        float4 b = tar[i];
        e = fenc(b.x); tmn = min(tmn, e); tmx = max(tmx, e);
        e = fenc(b.y); tmn = min(tmn, e); tmx = max(tmx, e);
        e = fenc(b.z); tmn = min(tmn, e); tmx = max(tmx, e);
        e = fenc(b.w); tmn = min(tmn, e); tmx = max(tmx, e);
    }
    #pragma unroll
    for (int o = 16; o > 0; o >>= 1) {
        rmn = min(rmn, __shfl_xor_sync(0xFFFFFFFFu, rmn, o));
        rmx = max(rmx, __shfl_xor_sync(0xFFFFFFFFu, rmx, o));
        tmn = min(tmn, __shfl_xor_sync(0xFFFFFFFFu, tmn, o));
        tmx = max(tmx, __shfl_xor_sync(0xFFFFFFFFu, tmx, o));
    }
    __syncthreads();
    if (lane == 0) {
        atomicMin(&s_mm[0], rmn); atomicMax(&s_mm[1], rmx);
        atomicMin(&s_mm[2], tmn); atomicMax(&s_mm[3], tmx);
    }
    __threadfence();                       // release: out-zero stores visible
    __syncthreads();

    // ---- grid sync (144 CTAs, 1 per SM -> co-resident, spin is safe) ----
    if (tid == 0) {
        volatile unsigned* sl = g_slot[bid];
        sl[0] = s_mm[0]; sl[1] = s_mm[1]; sl[2] = s_mm[2]; sl[3] = s_mm[3];
        __threadfence();
        unsigned prev = atomicAdd(&g_cnt, 1);
        unsigned target = prev - (prev % NBLK) + NBLK;   // end of this round
        while (*(volatile unsigned*)&g_cnt < target) { }
        __threadfence();                   // acquire
    }
    __syncthreads();

    // ---- reduce all block slots -> global min/max ----
    if (tid < 4) s_mm[tid] = (tid & 1) ? 0u : 0xFFFFFFFFu;
    __syncthreads();
    if (tid < NBLK) {
        volatile unsigned* sl = g_slot[tid];
        unsigned a0 = sl[0], a1 = sl[1], a2 = sl[2], a3 = sl[3];
        atomicMin(&s_mm[0], a0); atomicMax(&s_mm[1], a1);
        atomicMin(&s_mm[2], a2); atomicMax(&s_mm[3], a3);
    }
    __syncthreads();

    const float rmin = fdec(s_mm[0]), rmax = fdec(s_mm[1]);
    const float tmin = fdec(s_mm[2]), tmax = fdec(s_mm[3]);
    const float rs = 64.0f / (rmax - rmin);
    const float ts = 64.0f / (tmax - tmin);

    // ---- phase 2: per-batch joint histogram (images now L2-resident) ----
    const int batch = bid / BPB, sub = bid % BPB;
    const float4* rp = ref + (size_t)batch * (NPIX / 4);
    const float4* tp = tar + (size_t)batch * (NPIX / 4);
    for (int i = sub * TPB + tid; i < NPIX / 4; i += BPB * TPB) {
        float4 r4 = rp[i];
        float4 t4 = tp[i];
        accum(r4.x, t4.x, rmin, rs, tmin, ts, sh);
        accum(r4.y, t4.y, rmin, rs, tmin, ts, sh);
        accum(r4.z, t4.z, rmin, rs, tmin, ts, sh);
        accum(r4.w, t4.w, rmin, rs, tmin, ts, sh);
    }
    __syncthreads();

    // ---- phase 3: combine 4 replicas, unpack (scale 4096 = 1/EPS^2), flush ----
    float* o = out + (size_t)batch * NBINS * NBINS;
    for (int c = tid; c < NBINS * NBINS; c += TPB) {
        int row = c >> 6;
        int bt  = c & 63;
        unsigned acc = 0;
        #pragma unroll
        for (int r = 0; r < 4; r++) {
            int w = (bt + r) >> 2;
            int f = (bt + r) & 3;
            unsigned long long h = sh[r * REPW + row * ROWW + w];
            acc += (unsigned)(h >> (f * 16)) & 0xFFFFu;
        }
        atomicAdd(&o[c], (float)acc);
    }
}

extern "C" void kernel_launch(void* const* d_in, const int* in_sizes, int n_in,
                              void* d_out, int out_size) {
    const float4* img_ref = (const float4*)d_in[0];
    const float4* img_tar = (const float4*)d_in[1];
    float* out = (float*)d_out;
    k_fused<<<NBLK, TPB>>>(img_ref, img_tar, out);
}